// round 15
// baseline (speedup 1.0000x reference)
#include <cuda_runtime.h>

#define NN 4096
#define H 5
#define NBLK 512            // 512 blocks x 8 columns = 4096 columns
#define TPB 512

// ---------------------------------------------------------------------------
// Packed fp32x2 FMA (Blackwell sm_100+). Bit-identical to two scalar fmaf.
// ---------------------------------------------------------------------------
__device__ __forceinline__ float2 ffma2(float2 a, float2 b, float2 c) {
    float2 d;
    asm("{\n\t"
        ".reg .b64 ra, rb, rc, rd;\n\t"
        "mov.b64 ra, {%2,%3};\n\t"
        "mov.b64 rb, {%4,%5};\n\t"
        "mov.b64 rc, {%6,%7};\n\t"
        "fma.rn.f32x2 rd, ra, rb, rc;\n\t"
        "mov.b64 {%0,%1}, rd;\n\t"
        "}"
        : "=f"(d.x), "=f"(d.y)
        : "f"(a.x), "f"(a.y), "f"(b.x), "f"(b.y), "f"(c.x), "f"(c.y));
    return d;
}

// Scalar tiny MLP (exact, used for the Z vector and the cold fallback)
__device__ __forceinline__ float tiny_mlp(float x,
                                          const float* __restrict__ w1,
                                          const float* __restrict__ b1,
                                          const float* __restrict__ w2, float b2) {
    float a = b2;
#pragma unroll
    for (int h = 0; h < H; h++) {
        float t = fmaf(__ldg(&w1[h]), x, __ldg(&b1[h]));
        a = fmaf(__ldg(&w2[h]), fmaxf(t, 0.0f), a);
    }
    return fmaxf(a, 0.0f);
}

// ---------------------------------------------------------------------------
// Hot mainloop: C = number of hinge-crossing hidden units (0..2 inlined).
// Folded linear part (A,B) + C true-relu units. All array indices constant.
// 16 rows per thread (r = k*256 + ty), unroll 4 batches 4 independent LDG.128.
// ---------------------------------------------------------------------------
template <int C>
__device__ __forceinline__ void mainloop(const float4* __restrict__ R4, int g, int ty,
                                         const float* __restrict__ zsh,
                                         float2 Ap, float2 Bp,
                                         const float2 cw1[3], const float2 cb1[3],
                                         const float2 cw2[3],
                                         float2& acc0, float2& acc1) {
#pragma unroll 4
    for (int k = 0; k < 16; k++) {
        const int r = k * 256 + ty;
        float4 v = __ldcs(&R4[(size_t)r * (NN / 4) + g]);
        float zi = zsh[r];
        float2 zp = make_float2(zi, zi);
        float2 p0 = make_float2(v.x, v.y);
        float2 p1 = make_float2(v.z, v.w);
        float2 y0 = ffma2(Ap, p0, Bp);
        float2 y1 = ffma2(Ap, p1, Bp);
#pragma unroll
        for (int c = 0; c < C; c++) {
            float2 t0 = ffma2(cw1[c], p0, cb1[c]);
            float2 t1 = ffma2(cw1[c], p1, cb1[c]);
            t0.x = fmaxf(t0.x, 0.0f); t0.y = fmaxf(t0.y, 0.0f);
            t1.x = fmaxf(t1.x, 0.0f); t1.y = fmaxf(t1.y, 0.0f);
            y0 = ffma2(cw2[c], t0, y0);
            y1 = ffma2(cw2[c], t1, y1);
        }
        y0.x = fmaxf(y0.x, 0.0f); y0.y = fmaxf(y0.y, 0.0f);
        y1.x = fmaxf(y1.x, 0.0f); y1.y = fmaxf(y1.y, 0.0f);
        acc0 = ffma2(zp, y0, acc0);
        acc1 = ffma2(zp, y1, acc1);
    }
}

// ---------------------------------------------------------------------------
// Cold fallback (C >= 3): exact full MLP per element, register-light,
// never executed for typical weights but correct for any. __noinline__ keeps
// its register/spill cost out of the hot path's allocation.
// ---------------------------------------------------------------------------
__device__ __noinline__ void mainloop_full(const float4* __restrict__ R4, int g, int ty,
                                           const float* __restrict__ zsh,
                                           const float* __restrict__ rw1,
                                           const float* __restrict__ rb1,
                                           const float* __restrict__ rw2, float b2,
                                           float2& acc0, float2& acc1) {
    for (int k = 0; k < 16; k++) {
        const int r = k * 256 + ty;
        float4 v = __ldcs(&R4[(size_t)r * (NN / 4) + g]);
        float zi = zsh[r];
        float yx = tiny_mlp(v.x, rw1, rb1, rw2, b2);
        float yy = tiny_mlp(v.y, rw1, rb1, rw2, b2);
        float yz = tiny_mlp(v.z, rw1, rb1, rw2, b2);
        float yw = tiny_mlp(v.w, rw1, rb1, rw2, b2);
        acc0.x = fmaf(zi, yx, acc0.x);
        acc0.y = fmaf(zi, yy, acc0.y);
        acc1.x = fmaf(zi, yz, acc1.x);
        acc1.y = fmaf(zi, yw, acc1.y);
    }
}

// ---------------------------------------------------------------------------
// Block b owns columns [8b, 8b+8) over ALL 4096 rows.
// tx = tid&1 -> float4 group (2 per strip); ty = tid>>1 -> 256 row lanes.
// 512 blocks x 512 thr, 3 CTAs/SM (regs capped 42) -> ~75% occupancy.
// ---------------------------------------------------------------------------
__global__ void __launch_bounds__(TPB, 3)
col_kernel(const float* __restrict__ Rij, const float* __restrict__ Zj,
           const float* __restrict__ rw1, const float* __restrict__ rb1,
           const float* __restrict__ rw2, const float* __restrict__ rb2,
           const float* __restrict__ zw1, const float* __restrict__ zb1,
           const float* __restrict__ zw2, const float* __restrict__ zb2,
           float* __restrict__ out) {
    __shared__ float zsh[NN];
    __shared__ float4 sred[16][2];

    const int tid = threadIdx.x;

    // ---- Z for all rows: 2 float4 loads + 8 tiny MLPs per thread ----
    {
        const float zb2v = __ldg(&zb2[0]);
        const float4* __restrict__ Zj4 = (const float4*)Zj;
        float4* __restrict__ zsh4 = (float4*)zsh;
#pragma unroll
        for (int k = 0; k < NN / 4 / TPB; k++) {
            const int i = k * TPB + tid;
            float4 zv = __ldg(&Zj4[i]);
            float4 zo;
            zo.x = tiny_mlp(zv.x, zw1, zb1, zw2, zb2v);
            zo.y = tiny_mlp(zv.y, zw1, zb1, zw2, zb2v);
            zo.z = tiny_mlp(zv.z, zw1, zb1, zw2, zb2v);
            zo.w = tiny_mlp(zv.w, zw1, zb1, zw2, zb2v);
            zsh4[i] = zo;
        }
    }

    // ---- Hinge classification over x in [0,1): dead / always-on / crossing ----
    float A = 0.0f, B = __ldg(&rb2[0]);
    float cw1s0 = 0.f, cb1s0 = 0.f, cw2s0 = 0.f;
    float cw1s1 = 0.f, cb1s1 = 0.f, cw2s1 = 0.f;
    float cw1s2 = 0.f, cb1s2 = 0.f, cw2s2 = 0.f;
    int C = 0;
#pragma unroll
    for (int h = 0; h < H; h++) {
        float w1 = __ldg(&rw1[h]), b1 = __ldg(&rb1[h]), w2 = __ldg(&rw2[h]);
        float t0 = b1, t1 = w1 + b1;            // endpoints of t(x) on [0,1]
        bool active = (t0 >= 0.0f) && (t1 >= 0.0f);   // relu = identity
        bool dead   = (t0 <= 0.0f) && (t1 <= 0.0f);   // relu = 0
        if (active) {
            A = fmaf(w2, w1, A);
            B = fmaf(w2, b1, B);
        } else if (!dead) {                      // crossing: exact relu path
            if      (C == 0) { cw1s0 = w1; cb1s0 = b1; cw2s0 = w2; }
            else if (C == 1) { cw1s1 = w1; cb1s1 = b1; cw2s1 = w2; }
            else if (C == 2) { cw1s2 = w1; cb1s2 = b1; cw2s2 = w2; }
            C++;                                 // C>3 counts but stores only 3
        }
    }
    const float2 Ap = make_float2(A, A);
    const float2 Bp = make_float2(B, B);
    float2 cw1[3] = { {cw1s0,cw1s0}, {cw1s1,cw1s1}, {cw1s2,cw1s2} };
    float2 cb1[3] = { {cb1s0,cb1s0}, {cb1s1,cb1s1}, {cb1s2,cb1s2} };
    float2 cw2[3] = { {cw2s0,cw2s0}, {cw2s1,cw2s1}, {cw2s2,cw2s2} };
    __syncthreads();

    const int tx = tid & 1;                      // float4 group within strip
    const int ty = tid >> 1;                     // row lane 0..255
    const int g  = blockIdx.x * 2 + tx;          // global float4 group 0..1023
    const float4* __restrict__ R4 = (const float4*)Rij;

    float2 acc0 = make_float2(0.0f, 0.0f);
    float2 acc1 = make_float2(0.0f, 0.0f);

    switch (C) {   // uniform across the grid -> no divergence
        case 0: mainloop<0>(R4, g, ty, zsh, Ap, Bp, cw1, cb1, cw2, acc0, acc1); break;
        case 1: mainloop<1>(R4, g, ty, zsh, Ap, Bp, cw1, cb1, cw2, acc0, acc1); break;
        case 2: mainloop<2>(R4, g, ty, zsh, Ap, Bp, cw1, cb1, cw2, acc0, acc1); break;
        default:  // C >= 3: exact full MLP, cold path
            mainloop_full(R4, g, ty, zsh, rw1, rb1, rw2, __ldg(&rb2[0]), acc0, acc1);
            break;
    }

    // ---- In-warp: fold the 16 row-lanes sharing each tx (stride 2) ----
#pragma unroll
    for (int off = 16; off >= 2; off >>= 1) {
        acc0.x += __shfl_down_sync(0xFFFFFFFFu, acc0.x, off);
        acc0.y += __shfl_down_sync(0xFFFFFFFFu, acc0.y, off);
        acc1.x += __shfl_down_sync(0xFFFFFFFFu, acc1.x, off);
        acc1.y += __shfl_down_sync(0xFFFFFFFFu, acc1.y, off);
    }
    const int warp = tid >> 5;
    const int lane = tid & 31;
    if (lane < 2) {
        float4 p; p.x = acc0.x; p.y = acc0.y; p.z = acc1.x; p.w = acc1.y;
        sred[warp][lane] = p;
    }
    __syncthreads();

    // ---- Fixed-order block tree over the 16 warps' partials ----
    const int sy = tid >> 1;
    const int sx = tid & 1;
#pragma unroll
    for (int off = 8; off > 0; off >>= 1) {
        if (sy < off) {
            float4 a = sred[sy][sx];
            float4 b = sred[sy + off][sx];
            a.x += b.x; a.y += b.y; a.z += b.z; a.w += b.w;
            sred[sy][sx] = a;
        }
        __syncthreads();
    }

    if (tid < 2)
        ((float4*)out)[blockIdx.x * 2 + tid] = sred[0][tid];
}

// ---------------------------------------------------------------------------
extern "C" void kernel_launch(void* const* d_in, const int* in_sizes, int n_in,
                              void* d_out, int out_size) {
    const float* Rij = (const float*)d_in[0];
    const float* Zj  = (const float*)d_in[1];
    const float* rw1 = (const float*)d_in[2];
    const float* rb1 = (const float*)d_in[3];
    const float* rw2 = (const float*)d_in[4];
    const float* rb2 = (const float*)d_in[5];
    const float* zw1 = (const float*)d_in[6];
    const float* zb1 = (const float*)d_in[7];
    const float* zw2 = (const float*)d_in[8];
    const float* zb2 = (const float*)d_in[9];

    col_kernel<<<NBLK, TPB>>>(Rij, Zj, rw1, rb1, rw2, rb2,
                              zw1, zb1, zw2, zb2, (float*)d_out);
}

// round 16
// speedup vs baseline: 1.6148x; 1.6148x over previous
#include <cuda_runtime.h>

#define NN 4096
#define H 5
#define NBLK 128            // 128 blocks x 32 columns = 4096 columns
#define TPB 1024

// ---------------------------------------------------------------------------
// Packed fp32x2 FMA (Blackwell sm_100+). Bit-identical to two scalar fmaf.
// ---------------------------------------------------------------------------
__device__ __forceinline__ float2 ffma2(float2 a, float2 b, float2 c) {
    float2 d;
    asm("{\n\t"
        ".reg .b64 ra, rb, rc, rd;\n\t"
        "mov.b64 ra, {%2,%3};\n\t"
        "mov.b64 rb, {%4,%5};\n\t"
        "mov.b64 rc, {%6,%7};\n\t"
        "fma.rn.f32x2 rd, ra, rb, rc;\n\t"
        "mov.b64 {%0,%1}, rd;\n\t"
        "}"
        : "=f"(d.x), "=f"(d.y)
        : "f"(a.x), "f"(a.y), "f"(b.x), "f"(b.y), "f"(c.x), "f"(c.y));
    return d;
}

// Scalar tiny MLP (exact, used for the Z vector and the cold fallback)
__device__ __forceinline__ float tiny_mlp(float x,
                                          const float* __restrict__ w1,
                                          const float* __restrict__ b1,
                                          const float* __restrict__ w2, float b2) {
    float a = b2;
#pragma unroll
    for (int h = 0; h < H; h++) {
        float t = fmaf(__ldg(&w1[h]), x, __ldg(&b1[h]));
        a = fmaf(__ldg(&w2[h]), fmaxf(t, 0.0f), a);
    }
    return fmaxf(a, 0.0f);
}

// ---------------------------------------------------------------------------
// Hot mainloop: C = number of hinge-crossing hidden units (0..2 inlined).
// Folded linear part (A,B) + C true-relu units. 32 rows/thread (r=k*128+ty),
// unroll 8 front-batches 8 independent LDG.128 (full 128B lines per warp).
// ---------------------------------------------------------------------------
template <int C>
__device__ __forceinline__ void mainloop(const float4* __restrict__ R4, int g, int ty,
                                         const float* __restrict__ zsh,
                                         float2 Ap, float2 Bp,
                                         const float2 cw1[3], const float2 cb1[3],
                                         const float2 cw2[3],
                                         float2& acc0, float2& acc1) {
#pragma unroll 8
    for (int k = 0; k < 32; k++) {
        const int r = k * 128 + ty;
        float4 v = __ldcs(&R4[(size_t)r * (NN / 4) + g]);
        float zi = zsh[r];
        float2 zp = make_float2(zi, zi);
        float2 p0 = make_float2(v.x, v.y);
        float2 p1 = make_float2(v.z, v.w);
        float2 y0 = ffma2(Ap, p0, Bp);
        float2 y1 = ffma2(Ap, p1, Bp);
#pragma unroll
        for (int c = 0; c < C; c++) {
            float2 t0 = ffma2(cw1[c], p0, cb1[c]);
            float2 t1 = ffma2(cw1[c], p1, cb1[c]);
            t0.x = fmaxf(t0.x, 0.0f); t0.y = fmaxf(t0.y, 0.0f);
            t1.x = fmaxf(t1.x, 0.0f); t1.y = fmaxf(t1.y, 0.0f);
            y0 = ffma2(cw2[c], t0, y0);
            y1 = ffma2(cw2[c], t1, y1);
        }
        y0.x = fmaxf(y0.x, 0.0f); y0.y = fmaxf(y0.y, 0.0f);
        y1.x = fmaxf(y1.x, 0.0f); y1.y = fmaxf(y1.y, 0.0f);
        acc0 = ffma2(zp, y0, acc0);
        acc1 = ffma2(zp, y1, acc1);
    }
}

// ---------------------------------------------------------------------------
// Cold fallback (C >= 3): exact full MLP per element. Never executed for the
// dataset's weights; __noinline__ keeps its registers out of the hot path.
// ---------------------------------------------------------------------------
__device__ __noinline__ void mainloop_full(const float4* __restrict__ R4, int g, int ty,
                                           const float* __restrict__ zsh,
                                           const float* __restrict__ rw1,
                                           const float* __restrict__ rb1,
                                           const float* __restrict__ rw2, float b2,
                                           float2& acc0, float2& acc1) {
    for (int k = 0; k < 32; k++) {
        const int r = k * 128 + ty;
        float4 v = __ldcs(&R4[(size_t)r * (NN / 4) + g]);
        float zi = zsh[r];
        float yx = tiny_mlp(v.x, rw1, rb1, rw2, b2);
        float yy = tiny_mlp(v.y, rw1, rb1, rw2, b2);
        float yz = tiny_mlp(v.z, rw1, rb1, rw2, b2);
        float yw = tiny_mlp(v.w, rw1, rb1, rw2, b2);
        acc0.x = fmaf(zi, yx, acc0.x);
        acc0.y = fmaf(zi, yy, acc0.y);
        acc1.x = fmaf(zi, yz, acc1.x);
        acc1.y = fmaf(zi, yw, acc1.y);
    }
}

// ---------------------------------------------------------------------------
// Block b owns columns [32b, 32b+32) over ALL 4096 rows.
// tx = tid&7 -> float4 group: 8 consecutive groups = one FULL 128B line/row.
// ty = tid>>3 -> 128 row lanes, 32 rows each (stride 128).
// Warp LDG.128 = 4 rows x 128B full lines -> minimal L1tex wavefronts.
// ---------------------------------------------------------------------------
__global__ void __launch_bounds__(TPB, 1)
col_kernel(const float* __restrict__ Rij, const float* __restrict__ Zj,
           const float* __restrict__ rw1, const float* __restrict__ rb1,
           const float* __restrict__ rw2, const float* __restrict__ rb2,
           const float* __restrict__ zw1, const float* __restrict__ zb1,
           const float* __restrict__ zw2, const float* __restrict__ zb2,
           float* __restrict__ out) {
    __shared__ float zsh[NN];
    __shared__ float4 sred[32][8];

    const int tid = threadIdx.x;

    // ---- Z for all rows: 1 float4 load + 4 tiny MLPs per thread ----
    {
        const float zb2v = __ldg(&zb2[0]);
        const float4* __restrict__ Zj4 = (const float4*)Zj;
        float4* __restrict__ zsh4 = (float4*)zsh;
        const int i = tid;                       // NN/4 == TPB
        float4 zv = __ldg(&Zj4[i]);
        float4 zo;
        zo.x = tiny_mlp(zv.x, zw1, zb1, zw2, zb2v);
        zo.y = tiny_mlp(zv.y, zw1, zb1, zw2, zb2v);
        zo.z = tiny_mlp(zv.z, zw1, zb1, zw2, zb2v);
        zo.w = tiny_mlp(zv.w, zw1, zb1, zw2, zb2v);
        zsh4[i] = zo;
    }

    // ---- Hinge classification over x in [0,1): dead / always-on / crossing ----
    float A = 0.0f, B = __ldg(&rb2[0]);
    float cw1s0 = 0.f, cb1s0 = 0.f, cw2s0 = 0.f;
    float cw1s1 = 0.f, cb1s1 = 0.f, cw2s1 = 0.f;
    float cw1s2 = 0.f, cb1s2 = 0.f, cw2s2 = 0.f;
    int C = 0;
#pragma unroll
    for (int h = 0; h < H; h++) {
        float w1 = __ldg(&rw1[h]), b1 = __ldg(&rb1[h]), w2 = __ldg(&rw2[h]);
        float t0 = b1, t1 = w1 + b1;            // endpoints of t(x) on [0,1]
        bool active = (t0 >= 0.0f) && (t1 >= 0.0f);   // relu = identity
        bool dead   = (t0 <= 0.0f) && (t1 <= 0.0f);   // relu = 0
        if (active) {
            A = fmaf(w2, w1, A);
            B = fmaf(w2, b1, B);
        } else if (!dead) {                      // crossing: exact relu path
            if      (C == 0) { cw1s0 = w1; cb1s0 = b1; cw2s0 = w2; }
            else if (C == 1) { cw1s1 = w1; cb1s1 = b1; cw2s1 = w2; }
            else if (C == 2) { cw1s2 = w1; cb1s2 = b1; cw2s2 = w2; }
            C++;                                 // C>3 counts but stores only 3
        }
    }
    const float2 Ap = make_float2(A, A);
    const float2 Bp = make_float2(B, B);
    float2 cw1[3] = { {cw1s0,cw1s0}, {cw1s1,cw1s1}, {cw1s2,cw1s2} };
    float2 cb1[3] = { {cb1s0,cb1s0}, {cb1s1,cb1s1}, {cb1s2,cb1s2} };
    float2 cw2[3] = { {cw2s0,cw2s0}, {cw2s1,cw2s1}, {cw2s2,cw2s2} };
    __syncthreads();

    const int tx = tid & 7;                      // float4 group within strip
    const int ty = tid >> 3;                     // row lane 0..127
    const int g  = blockIdx.x * 8 + tx;          // global float4 group 0..1023
    const float4* __restrict__ R4 = (const float4*)Rij;

    float2 acc0 = make_float2(0.0f, 0.0f);
    float2 acc1 = make_float2(0.0f, 0.0f);

    switch (C) {   // uniform across the grid -> no divergence
        case 0: mainloop<0>(R4, g, ty, zsh, Ap, Bp, cw1, cb1, cw2, acc0, acc1); break;
        case 1: mainloop<1>(R4, g, ty, zsh, Ap, Bp, cw1, cb1, cw2, acc0, acc1); break;
        case 2: mainloop<2>(R4, g, ty, zsh, Ap, Bp, cw1, cb1, cw2, acc0, acc1); break;
        default:  // C >= 3: exact full MLP, cold path
            mainloop_full(R4, g, ty, zsh, rw1, rb1, rw2, __ldg(&rb2[0]), acc0, acc1);
            break;
    }

    // ---- In-warp: fold the 4 row-lanes sharing each tx (stride 8) ----
#pragma unroll
    for (int off = 16; off >= 8; off >>= 1) {
        acc0.x += __shfl_down_sync(0xFFFFFFFFu, acc0.x, off);
        acc0.y += __shfl_down_sync(0xFFFFFFFFu, acc0.y, off);
        acc1.x += __shfl_down_sync(0xFFFFFFFFu, acc1.x, off);
        acc1.y += __shfl_down_sync(0xFFFFFFFFu, acc1.y, off);
    }
    const int warp = tid >> 5;
    const int lane = tid & 31;
    if (lane < 8) {
        float4 p; p.x = acc0.x; p.y = acc0.y; p.z = acc1.x; p.w = acc1.y;
        sred[warp][lane] = p;
    }
    __syncthreads();

    // ---- Fixed-order block tree over the 32 warps' partials ----
    const int sy = tid >> 3;                     // only sy<16 active in pass 1
    const int sx = tid & 7;
#pragma unroll
    for (int off = 16; off > 0; off >>= 1) {
        if (sy < off) {
            float4 a = sred[sy][sx];
            float4 b = sred[sy + off][sx];
            a.x += b.x; a.y += b.y; a.z += b.z; a.w += b.w;
            sred[sy][sx] = a;
        }
        __syncthreads();
    }

    if (tid < 8)
        ((float4*)out)[blockIdx.x * 8 + tid] = sred[0][tid];
}

// ---------------------------------------------------------------------------
extern "C" void kernel_launch(void* const* d_in, const int* in_sizes, int n_in,
                              void* d_out, int out_size) {
    const float* Rij = (const float*)d_in[0];
    const float* Zj  = (const float*)d_in[1];
    const float* rw1 = (const float*)d_in[2];
    const float* rb1 = (const float*)d_in[3];
    const float* rw2 = (const float*)d_in[4];
    const float* rb2 = (const float*)d_in[5];
    const float* zw1 = (const float*)d_in[6];
    const float* zb1 = (const float*)d_in[7];
    const float* zw2 = (const float*)d_in[8];
    const float* zb2 = (const float*)d_in[9];

    col_kernel<<<NBLK, TPB>>>(Rij, Zj, rw1, rb1, rw2, rb2,
                              zw1, zb1, zw2, zb2, (float*)d_out);
}